// round 7
// baseline (speedup 1.0000x reference)
#include <cuda_runtime.h>
#include <cuda_bf16.h>
#include <cstdint>

#define HID  512
#define BATCH 4
#define SEQ  4096

// Scratch (static device globals; allocation-free per harness rules)
// q | k | vt  (vt stored transposed per batch: [HID][SEQ])
__device__ float g_qkv[(size_t)3 * BATCH * SEQ * HID];          // 96 MB
__device__ float g_scores[(size_t)BATCH * SEQ * SEQ];           // 256 MB

// ---------------------------------------------------------------------------
// helpers
// ---------------------------------------------------------------------------
__device__ __forceinline__ uint32_t s2u(const void* p) {
    uint32_t a;
    asm("{ .reg .u64 t; cvta.to.shared.u64 t, %1; cvt.u32.u64 %0, t; }"
        : "=r"(a) : "l"(p));
    return a;
}

// f = hi + lo, both bf16; packed pairs into bf16x2 words
__device__ __forceinline__ void split2(float f0, float f1, uint32_t& hi, uint32_t& lo) {
    asm("cvt.rn.bf16x2.f32 %0, %2, %1;" : "=r"(hi) : "f"(f0), "f"(f1));
    float h0 = __uint_as_float(hi << 16);
    float h1 = __uint_as_float(hi & 0xffff0000u);
    float l0 = f0 - h0;
    float l1 = f1 - h1;
    asm("cvt.rn.bf16x2.f32 %0, %2, %1;" : "=r"(lo) : "f"(l0), "f"(l1));
}

__device__ __forceinline__ void mma16(float c[4],
                                      uint32_t a0, uint32_t a1, uint32_t a2, uint32_t a3,
                                      uint32_t b0, uint32_t b1) {
    asm volatile(
        "mma.sync.aligned.m16n8k16.row.col.f32.bf16.bf16.f32 "
        "{%0,%1,%2,%3}, {%4,%5,%6,%7}, {%8,%9}, {%0,%1,%2,%3};\n"
        : "+f"(c[0]), "+f"(c[1]), "+f"(c[2]), "+f"(c[3])
        : "r"(a0), "r"(a1), "r"(a2), "r"(a3), "r"(b0), "r"(b1));
}

__device__ __forceinline__ void ldsm4(uint32_t addr, uint32_t r[4]) {
    asm volatile("ldmatrix.sync.aligned.m8n8.x4.shared.b16 {%0,%1,%2,%3}, [%4];"
                 : "=r"(r[0]), "=r"(r[1]), "=r"(r[2]), "=r"(r[3]) : "r"(addr));
}

// ---------------------------------------------------------------------------
// GEMM NT (bf16 3-split, double-buffered, ldmatrix): C[m,n] = sum_k A[m,k]B[n,k]
// BM=128, BN=128, BK=16 floats. 128 threads = 4 warps (2x2), warp tile 64x64.
// Dynamic smem 48KB: 2 buffers x (A hi/lo + B hi/lo) in [row][12] layout.
// Fragment loads via ldmatrix.x4 (16 per warp-stage instead of 64 LDS).
// tout=1: write C transposed per batch (used for the V projection -> Vt).
// ---------------------------------------------------------------------------
#define STG 1536   // uint32 per buffer per array: 128*12

__global__ void __launch_bounds__(128) gemm_nt(
    const float* __restrict__ A, const float* __restrict__ B, float* __restrict__ C,
    int lda, int ldb, int ldc, int Kdim,
    long long sA_, long long sB_, long long sC_, int tout)
{
    extern __shared__ __align__(16) uint32_t dsm[];
    uint32_t* sAhi = dsm;                 // [2][STG]
    uint32_t* sAlo = dsm + 2 * STG;
    uint32_t* sBhi = dsm + 4 * STG;
    uint32_t* sBlo = dsm + 6 * STG;
    const uint32_t sb = s2u(dsm);

    const float* Ag = A + (long long)blockIdx.z * sA_ + (long long)blockIdx.y * 128 * lda;
    const float* Bg = B + (long long)blockIdx.z * sB_ + (long long)blockIdx.x * 128 * ldb;

    const int tid  = threadIdx.x;
    const int warp = tid >> 5, lane = tid & 31;
    const int wm = (warp >> 1) * 64, wn = (warp & 1) * 64;
    const int lr = lane >> 2, lc = lane & 3;

    // ldmatrix per-lane offset: lanes 0-7 -> rows r+0..7 word 0 (m0-7,k0-7),
    // 8-15 -> rows +8 word 0, 16-23 -> rows +0 word 4, 24-31 -> rows +8 word 4
    const int g = lane >> 3, l8 = lane & 7;
    const uint32_t loff = ((((g & 1) * 8 + l8) * 12) + (g >> 1) * 4) * 4;

    // staging coords
    const int rs = tid >> 2;
    const int cs = (tid & 3) * 4;        // float col
    const int cw = (tid & 3) * 2;        // bf16x2 word col

    float acc[4][8][4] = {};

    float4 va[4], vb[4];
    auto load_gmem = [&](int k0) {
#pragma unroll
        for (int p = 0; p < 4; p++) {
            va[p] = *(const float4*)(Ag + (long long)(rs + p * 32) * lda + k0 + cs);
            vb[p] = *(const float4*)(Bg + (long long)(rs + p * 32) * ldb + k0 + cs);
        }
    };
    auto store_smem = [&](int buf) {
        uint32_t* pAh = sAhi + buf * STG;
        uint32_t* pAl = sAlo + buf * STG;
        uint32_t* pBh = sBhi + buf * STG;
        uint32_t* pBl = sBlo + buf * STG;
#pragma unroll
        for (int p = 0; p < 4; p++) {
            int ro = (rs + p * 32) * 12;
            uint32_t h0, l0, h1, l1;
            split2(va[p].x, va[p].y, h0, l0);
            split2(va[p].z, va[p].w, h1, l1);
            pAh[ro + cw] = h0;  pAh[ro + cw + 1] = h1;
            pAl[ro + cw] = l0;  pAl[ro + cw + 1] = l1;
            split2(vb[p].x, vb[p].y, h0, l0);
            split2(vb[p].z, vb[p].w, h1, l1);
            pBh[ro + cw] = h0;  pBh[ro + cw + 1] = h1;
            pBl[ro + cw] = l0;  pBl[ro + cw + 1] = l1;
        }
    };
    auto compute = [&](int buf) {
        const uint32_t bufB = (uint32_t)buf * STG * 4;
        uint32_t aAh = sb + bufB + wm * 48 + loff;               // 12 words*4B=48B/row
        uint32_t aAl = aAh + 2 * STG * 4;
        uint32_t aBh = sb + 4 * STG * 4 + bufB + wn * 48 + loff;
        uint32_t aBl = aBh + 2 * STG * 4;

        uint32_t Ah[4][4], Al[4][4], Bh[4][4], Bl[4][4];
#pragma unroll
        for (int mi = 0; mi < 4; mi++) {
            ldsm4(aAh + mi * 768, Ah[mi]);    // 16 rows * 48B
            ldsm4(aAl + mi * 768, Al[mi]);
        }
#pragma unroll
        for (int pr = 0; pr < 4; pr++) {
            ldsm4(aBh + pr * 768, Bh[pr]);    // covers ni=2pr, 2pr+1
            ldsm4(aBl + pr * 768, Bl[pr]);
        }
#pragma unroll
        for (int pr = 0; pr < 4; pr++)
#pragma unroll
            for (int s = 0; s < 2; s++) {
                int ni = 2 * pr + s;
                uint32_t bh0 = Bh[pr][s], bh1 = Bh[pr][s + 2];
                uint32_t bl0 = Bl[pr][s], bl1 = Bl[pr][s + 2];
#pragma unroll
                for (int mi = 0; mi < 4; mi++) {
                    mma16(acc[mi][ni], Ah[mi][0], Ah[mi][1], Ah[mi][2], Ah[mi][3], bh0, bh1);
                    mma16(acc[mi][ni], Ah[mi][0], Ah[mi][1], Ah[mi][2], Ah[mi][3], bl0, bl1);
                    mma16(acc[mi][ni], Al[mi][0], Al[mi][1], Al[mi][2], Al[mi][3], bh0, bh1);
                }
            }
    };

    // prologue
    load_gmem(0);
    store_smem(0);
    __syncthreads();

    int buf = 0;
    for (int k0 = 0; k0 < Kdim; k0 += 16) {
        bool more = (k0 + 16) < Kdim;
        if (more) load_gmem(k0 + 16);      // prefetch overlaps compute
        compute(buf);
        if (more) {
            store_smem(buf ^ 1);
            __syncthreads();
            buf ^= 1;
        }
    }

    if (!tout) {
        float* Cg = C + (long long)blockIdx.z * sC_ + (long long)blockIdx.y * 128 * ldc
                      + (long long)blockIdx.x * 128;
#pragma unroll
        for (int mi = 0; mi < 4; mi++)
#pragma unroll
            for (int ni = 0; ni < 8; ni++) {
                int rr = wm + mi * 16 + lr;
                int cc = wn + ni * 8 + lc * 2;
                *(float2*)(Cg + (long long)rr * ldc + cc)       = make_float2(acc[mi][ni][0], acc[mi][ni][1]);
                *(float2*)(Cg + (long long)(rr + 8) * ldc + cc) = make_float2(acc[mi][ni][2], acc[mi][ni][3]);
            }
    } else {
        // transposed write: global row R = (b,s), col h  ->  C[b][h][s]
#pragma unroll
        for (int mi = 0; mi < 4; mi++)
#pragma unroll
            for (int ni = 0; ni < 8; ni++) {
                int R  = blockIdx.y * 128 + wm + mi * 16 + lr;
                int hc = blockIdx.x * 128 + wn + ni * 8 + lc * 2;
                int b  = R >> 12, s = R & (SEQ - 1);
                float* base = C + (long long)b * HID * SEQ;
                base[(long long)hc * SEQ + s]           = acc[mi][ni][0];
                base[(long long)(hc + 1) * SEQ + s]     = acc[mi][ni][1];
                base[(long long)hc * SEQ + s + 8]       = acc[mi][ni][2];
                base[(long long)(hc + 1) * SEQ + s + 8] = acc[mi][ni][3];
            }
    }
}

// ---------------------------------------------------------------------------
// Row softmax over SEQ=4096, with /sqrt(H) scale folded in.
// ---------------------------------------------------------------------------
__global__ void __launch_bounds__(256) softmax_kernel(float* __restrict__ S, float scale) {
    long long row = blockIdx.x;
    float* p = S + row * (long long)SEQ;
    const int tid = threadIdx.x;

    float4 v[4];
    float m = -3.4e38f;
#pragma unroll
    for (int i = 0; i < 4; i++) {
        v[i] = ((const float4*)p)[tid + i * 256];
        m = fmaxf(m, fmaxf(fmaxf(v[i].x, v[i].y), fmaxf(v[i].z, v[i].w)));
    }

    __shared__ float red[8];
#pragma unroll
    for (int o = 16; o; o >>= 1) m = fmaxf(m, __shfl_xor_sync(0xffffffffu, m, o));
    if ((tid & 31) == 0) red[tid >> 5] = m;
    __syncthreads();
    m = red[0];
#pragma unroll
    for (int i = 1; i < 8; i++) m = fmaxf(m, red[i]);

    float sum = 0.f;
#pragma unroll
    for (int i = 0; i < 4; i++) {
        v[i].x = __expf((v[i].x - m) * scale);
        v[i].y = __expf((v[i].y - m) * scale);
        v[i].z = __expf((v[i].z - m) * scale);
        v[i].w = __expf((v[i].w - m) * scale);
        sum += (v[i].x + v[i].y) + (v[i].z + v[i].w);
    }
#pragma unroll
    for (int o = 16; o; o >>= 1) sum += __shfl_xor_sync(0xffffffffu, sum, o);
    __syncthreads();
    if ((tid & 31) == 0) red[tid >> 5] = sum;
    __syncthreads();
    float tot = 0.f;
#pragma unroll
    for (int i = 0; i < 8; i++) tot += red[i];
    float inv = 1.0f / tot;

#pragma unroll
    for (int i = 0; i < 4; i++) {
        v[i].x *= inv; v[i].y *= inv; v[i].z *= inv; v[i].w *= inv;
        ((float4*)p)[tid + i * 256] = v[i];
    }
}

// ---------------------------------------------------------------------------
// Launcher
// ---------------------------------------------------------------------------
#define GEMM_SMEM 49152

extern "C" void kernel_launch(void* const* d_in, const int* in_sizes, int n_in,
                              void* d_out, int out_size) {
    const float* x  = (const float*)d_in[0];
    const float* Wq = (const float*)d_in[1];
    const float* Wk = (const float*)d_in[2];
    const float* Wv = (const float*)d_in[3];
    float* out = (float*)d_out;

    float *qp, *sp;
    cudaGetSymbolAddress((void**)&qp, g_qkv);
    cudaGetSymbolAddress((void**)&sp, g_scores);
    float* kp  = qp + (long long)BATCH * SEQ * HID;
    float* vtp = kp + (long long)BATCH * SEQ * HID;     // transposed V: [b][h][s]

    cudaFuncSetAttribute(gemm_nt, cudaFuncAttributeMaxDynamicSharedMemorySize, GEMM_SMEM);

    dim3 blk(128);

    // 1) QKV projections: y = x W^T  (M=16384, N=512, K=512); V written transposed
    dim3 gq(HID / 128, (BATCH * SEQ) / 128, 1);
    gemm_nt<<<gq, blk, GEMM_SMEM>>>(x, Wq, qp,  HID, HID, HID, HID, 0, 0, 0, 0);
    gemm_nt<<<gq, blk, GEMM_SMEM>>>(x, Wk, kp,  HID, HID, HID, HID, 0, 0, 0, 0);
    gemm_nt<<<gq, blk, GEMM_SMEM>>>(x, Wv, vtp, HID, HID, HID, HID, 0, 0, 0, 1);

    // 2) S = Q K^T  (batched: M=N=4096, K=512)
    dim3 gs(SEQ / 128, SEQ / 128, BATCH);
    gemm_nt<<<gs, blk, GEMM_SMEM>>>(qp, kp, sp, HID, HID, SEQ, HID,
                                    (long long)SEQ * HID, (long long)SEQ * HID,
                                    (long long)SEQ * SEQ, 0);

    // 3) softmax rows with 1/sqrt(H) scale
    softmax_kernel<<<BATCH * SEQ, 256>>>(sp, 0.044194173824159216f);

    // 4) O = P Vt^T  (NT: M=4096, N=512, K=4096, batched)
    dim3 gp(HID / 128, SEQ / 128, BATCH);
    gemm_nt<<<gp, blk, GEMM_SMEM>>>(sp, vtp, out, SEQ, SEQ, HID, SEQ,
                                    (long long)SEQ * SEQ, (long long)HID * SEQ,
                                    (long long)SEQ * HID, 0);
}

// round 8
// speedup vs baseline: 1.1326x; 1.1326x over previous
#include <cuda_runtime.h>
#include <cuda_bf16.h>
#include <cstdint>

#define HID  512
#define BATCH 4
#define SEQ  4096

// Scratch (static device globals; allocation-free per harness rules)
// q | k | vt  (vt stored transposed per batch: [HID][SEQ])
__device__ float g_qkv[(size_t)3 * BATCH * SEQ * HID];          // 96 MB
__device__ float g_scores[(size_t)BATCH * SEQ * SEQ];           // 256 MB

// ---------------------------------------------------------------------------
// bf16 split helpers: f = hi + lo with hi,lo bf16; pack pairs into bf16x2 words
// ---------------------------------------------------------------------------
__device__ __forceinline__ void split2(float f0, float f1, uint32_t& hi, uint32_t& lo) {
    asm("cvt.rn.bf16x2.f32 %0, %2, %1;" : "=r"(hi) : "f"(f0), "f"(f1));
    float h0 = __uint_as_float(hi << 16);
    float h1 = __uint_as_float(hi & 0xffff0000u);
    float l0 = f0 - h0;
    float l1 = f1 - h1;
    asm("cvt.rn.bf16x2.f32 %0, %2, %1;" : "=r"(lo) : "f"(l0), "f"(l1));
}

__device__ __forceinline__ void mma16(float c[4],
                                      uint32_t a0, uint32_t a1, uint32_t a2, uint32_t a3,
                                      uint32_t b0, uint32_t b1) {
    asm volatile(
        "mma.sync.aligned.m16n8k16.row.col.f32.bf16.bf16.f32 "
        "{%0,%1,%2,%3}, {%4,%5,%6,%7}, {%8,%9}, {%0,%1,%2,%3};\n"
        : "+f"(c[0]), "+f"(c[1]), "+f"(c[2]), "+f"(c[3])
        : "r"(a0), "r"(a1), "r"(a2), "r"(a3), "r"(b0), "r"(b1));
}

// ---------------------------------------------------------------------------
// GEMM NT (bf16 3-split, BK=32, double-buffered): C[m,n] = sum_k A[m,k]B[n,k]
// BM=128, BN=128, BK=32 floats. 128 threads = 4 warps (2x2), warp tile 64x64.
// Dynamic smem 80KB: 2 buffers x (A hi/lo + B hi/lo) in [row][20] layout
// (16 data words + 4 pad; banks 20*r mod 32 distinct -> conflict-free).
// One __syncthreads per 32-K stage; gmem prefetch in 2 halves interleaved
// with the 2 k16 compute chunks.  tout=1: write C transposed (V -> Vt).
// ---------------------------------------------------------------------------
#define STRD 20
#define STG  2560   // uint32 per buffer per array: 128*20

__global__ void __launch_bounds__(128) gemm_nt(
    const float* __restrict__ A, const float* __restrict__ B, float* __restrict__ C,
    int lda, int ldb, int ldc, int Kdim,
    long long sA_, long long sB_, long long sC_, int tout)
{
    extern __shared__ __align__(16) uint32_t dsm[];
    uint32_t* sAhi = dsm;                 // [2][STG]
    uint32_t* sAlo = dsm + 2 * STG;
    uint32_t* sBhi = dsm + 4 * STG;
    uint32_t* sBlo = dsm + 6 * STG;

    const float* Ag = A + (long long)blockIdx.z * sA_ + (long long)blockIdx.y * 128 * lda;
    const float* Bg = B + (long long)blockIdx.z * sB_ + (long long)blockIdx.x * 128 * ldb;

    const int tid  = threadIdx.x;
    const int warp = tid >> 5, lane = tid & 31;
    const int wm = (warp >> 1) * 64, wn = (warp & 1) * 64;
    const int lr = lane >> 2, lc = lane & 3;

    // staging coords: thread covers rows p*32 + (tid>>2), float cols (tid&3)*4
    const int rs = tid >> 2;
    const int cs = (tid & 3) * 4;        // float col within 16-col half
    const int cw = (tid & 3) * 2;        // bf16x2 word col within half

    float acc[4][8][4] = {};

    float4 va[4], vb[4];
    auto loadH = [&](int kf) {           // load one 16-float-col half at col kf
#pragma unroll
        for (int p = 0; p < 4; p++) {
            va[p] = *(const float4*)(Ag + (long long)(rs + p * 32) * lda + kf + cs);
            vb[p] = *(const float4*)(Bg + (long long)(rs + p * 32) * ldb + kf + cs);
        }
    };
    auto storeH = [&](int buf, int h) {  // store held regs into half h of buf
        uint32_t* pAh = sAhi + buf * STG;
        uint32_t* pAl = sAlo + buf * STG;
        uint32_t* pBh = sBhi + buf * STG;
        uint32_t* pBl = sBlo + buf * STG;
        const int cb = h * 8 + cw;
#pragma unroll
        for (int p = 0; p < 4; p++) {
            int ro = (rs + p * 32) * STRD;
            uint32_t h0, l0, h1, l1;
            split2(va[p].x, va[p].y, h0, l0);
            split2(va[p].z, va[p].w, h1, l1);
            pAh[ro + cb] = h0;  pAh[ro + cb + 1] = h1;
            pAl[ro + cb] = l0;  pAl[ro + cb + 1] = l1;
            split2(vb[p].x, vb[p].y, h0, l0);
            split2(vb[p].z, vb[p].w, h1, l1);
            pBh[ro + cb] = h0;  pBh[ro + cb + 1] = h1;
            pBl[ro + cb] = l0;  pBl[ro + cb + 1] = l1;
        }
    };
    auto compute = [&](int buf, int kc) {   // one k16 chunk (kc = 0 or 1)
        const uint32_t* pAh = sAhi + buf * STG;
        const uint32_t* pAl = sAlo + buf * STG;
        const uint32_t* pBh = sBhi + buf * STG;
        const uint32_t* pBl = sBlo + buf * STG;
        const int cb = kc * 8;
        uint32_t ah[4][4], al[4][4];
#pragma unroll
        for (int mi = 0; mi < 4; mi++) {
            int r0 = (wm + mi * 16 + lr) * STRD + cb;
            ah[mi][0] = pAh[r0            + lc    ];  al[mi][0] = pAl[r0            + lc    ];
            ah[mi][1] = pAh[r0 + 8 * STRD + lc    ];  al[mi][1] = pAl[r0 + 8 * STRD + lc    ];
            ah[mi][2] = pAh[r0            + lc + 4];  al[mi][2] = pAl[r0            + lc + 4];
            ah[mi][3] = pAh[r0 + 8 * STRD + lc + 4];  al[mi][3] = pAl[r0 + 8 * STRD + lc + 4];
        }
#pragma unroll
        for (int ni = 0; ni < 8; ni++) {
            int n0 = (wn + ni * 8 + lr) * STRD + cb;
            uint32_t bh0 = pBh[n0 + lc], bh1 = pBh[n0 + lc + 4];
            uint32_t bl0 = pBl[n0 + lc], bl1 = pBl[n0 + lc + 4];
#pragma unroll
            for (int mi = 0; mi < 4; mi++) {
                mma16(acc[mi][ni], ah[mi][0], ah[mi][1], ah[mi][2], ah[mi][3], bh0, bh1);
                mma16(acc[mi][ni], ah[mi][0], ah[mi][1], ah[mi][2], ah[mi][3], bl0, bl1);
                mma16(acc[mi][ni], al[mi][0], al[mi][1], al[mi][2], al[mi][3], bh0, bh1);
            }
        }
    };

    // prologue: fill buffer 0 (both halves)
    loadH(0);  storeH(0, 0);
    loadH(16); storeH(0, 1);
    __syncthreads();

    int buf = 0;
    for (int k0 = 0; k0 < Kdim; k0 += 32) {
        bool more = (k0 + 32) < Kdim;
        if (more) loadH(k0 + 32);            // next stage half 0
        compute(buf, 0);
        if (more) { storeH(buf ^ 1, 0); loadH(k0 + 48); }   // next half 1
        compute(buf, 1);
        if (more) {
            storeH(buf ^ 1, 1);
            __syncthreads();
            buf ^= 1;
        }
    }

    if (!tout) {
        float* Cg = C + (long long)blockIdx.z * sC_ + (long long)blockIdx.y * 128 * ldc
                      + (long long)blockIdx.x * 128;
#pragma unroll
        for (int mi = 0; mi < 4; mi++)
#pragma unroll
            for (int ni = 0; ni < 8; ni++) {
                int rr = wm + mi * 16 + lr;
                int cc = wn + ni * 8 + lc * 2;
                *(float2*)(Cg + (long long)rr * ldc + cc)       = make_float2(acc[mi][ni][0], acc[mi][ni][1]);
                *(float2*)(Cg + (long long)(rr + 8) * ldc + cc) = make_float2(acc[mi][ni][2], acc[mi][ni][3]);
            }
    } else {
        // transposed write: global row R = (b,s), col h  ->  C[b][h][s]
#pragma unroll
        for (int mi = 0; mi < 4; mi++)
#pragma unroll
            for (int ni = 0; ni < 8; ni++) {
                int R  = blockIdx.y * 128 + wm + mi * 16 + lr;
                int hc = blockIdx.x * 128 + wn + ni * 8 + lc * 2;
                int b  = R >> 12, s = R & (SEQ - 1);
                float* base = C + (long long)b * HID * SEQ;
                base[(long long)hc * SEQ + s]           = acc[mi][ni][0];
                base[(long long)(hc + 1) * SEQ + s]     = acc[mi][ni][1];
                base[(long long)hc * SEQ + s + 8]       = acc[mi][ni][2];
                base[(long long)(hc + 1) * SEQ + s + 8] = acc[mi][ni][3];
            }
    }
}

// ---------------------------------------------------------------------------
// Row softmax over SEQ=4096, with /sqrt(H) scale folded in.
// ---------------------------------------------------------------------------
__global__ void __launch_bounds__(256) softmax_kernel(float* __restrict__ S, float scale) {
    long long row = blockIdx.x;
    float* p = S + row * (long long)SEQ;
    const int tid = threadIdx.x;

    float4 v[4];
    float m = -3.4e38f;
#pragma unroll
    for (int i = 0; i < 4; i++) {
        v[i] = ((const float4*)p)[tid + i * 256];
        m = fmaxf(m, fmaxf(fmaxf(v[i].x, v[i].y), fmaxf(v[i].z, v[i].w)));
    }

    __shared__ float red[8];
#pragma unroll
    for (int o = 16; o; o >>= 1) m = fmaxf(m, __shfl_xor_sync(0xffffffffu, m, o));
    if ((tid & 31) == 0) red[tid >> 5] = m;
    __syncthreads();
    m = red[0];
#pragma unroll
    for (int i = 1; i < 8; i++) m = fmaxf(m, red[i]);

    float sum = 0.f;
#pragma unroll
    for (int i = 0; i < 4; i++) {
        v[i].x = __expf((v[i].x - m) * scale);
        v[i].y = __expf((v[i].y - m) * scale);
        v[i].z = __expf((v[i].z - m) * scale);
        v[i].w = __expf((v[i].w - m) * scale);
        sum += (v[i].x + v[i].y) + (v[i].z + v[i].w);
    }
#pragma unroll
    for (int o = 16; o; o >>= 1) sum += __shfl_xor_sync(0xffffffffu, sum, o);
    __syncthreads();
    if ((tid & 31) == 0) red[tid >> 5] = sum;
    __syncthreads();
    float tot = 0.f;
#pragma unroll
    for (int i = 0; i < 8; i++) tot += red[i];
    float inv = 1.0f / tot;

#pragma unroll
    for (int i = 0; i < 4; i++) {
        v[i].x *= inv; v[i].y *= inv; v[i].z *= inv; v[i].w *= inv;
        ((float4*)p)[tid + i * 256] = v[i];
    }
}

// ---------------------------------------------------------------------------
// Launcher
// ---------------------------------------------------------------------------
#define GEMM_SMEM 81920

extern "C" void kernel_launch(void* const* d_in, const int* in_sizes, int n_in,
                              void* d_out, int out_size) {
    const float* x  = (const float*)d_in[0];
    const float* Wq = (const float*)d_in[1];
    const float* Wk = (const float*)d_in[2];
    const float* Wv = (const float*)d_in[3];
    float* out = (float*)d_out;

    float *qp, *sp;
    cudaGetSymbolAddress((void**)&qp, g_qkv);
    cudaGetSymbolAddress((void**)&sp, g_scores);
    float* kp  = qp + (long long)BATCH * SEQ * HID;
    float* vtp = kp + (long long)BATCH * SEQ * HID;     // transposed V: [b][h][s]

    cudaFuncSetAttribute(gemm_nt, cudaFuncAttributeMaxDynamicSharedMemorySize, GEMM_SMEM);

    dim3 blk(128);

    // 1) QKV projections: y = x W^T  (M=16384, N=512, K=512); V written transposed
    dim3 gq(HID / 128, (BATCH * SEQ) / 128, 1);
    gemm_nt<<<gq, blk, GEMM_SMEM>>>(x, Wq, qp,  HID, HID, HID, HID, 0, 0, 0, 0);
    gemm_nt<<<gq, blk, GEMM_SMEM>>>(x, Wk, kp,  HID, HID, HID, HID, 0, 0, 0, 0);
    gemm_nt<<<gq, blk, GEMM_SMEM>>>(x, Wv, vtp, HID, HID, HID, HID, 0, 0, 0, 1);

    // 2) S = Q K^T  (batched: M=N=4096, K=512)
    dim3 gs(SEQ / 128, SEQ / 128, BATCH);
    gemm_nt<<<gs, blk, GEMM_SMEM>>>(qp, kp, sp, HID, HID, SEQ, HID,
                                    (long long)SEQ * HID, (long long)SEQ * HID,
                                    (long long)SEQ * SEQ, 0);

    // 3) softmax rows with 1/sqrt(H) scale
    softmax_kernel<<<BATCH * SEQ, 256>>>(sp, 0.044194173824159216f);

    // 4) O = P Vt^T  (NT: M=4096, N=512, K=4096, batched)
    dim3 gp(HID / 128, SEQ / 128, BATCH);
    gemm_nt<<<gp, blk, GEMM_SMEM>>>(sp, vtp, out, SEQ, SEQ, HID, SEQ,
                                    (long long)SEQ * SEQ, (long long)HID * SEQ,
                                    (long long)SEQ * HID, 0);
}

// round 9
// speedup vs baseline: 1.4578x; 1.2871x over previous
#include <cuda_runtime.h>
#include <cuda_bf16.h>
#include <cuda_fp16.h>
#include <cstdint>

#define HID  512
#define BATCH 4
#define SEQ  4096

// Scratch (static device globals; allocation-free per harness rules)
// q | k | vt  (vt stored transposed per batch: [HID][SEQ])
__device__ float g_qkv[(size_t)3 * BATCH * SEQ * HID];          // 96 MB
__device__ float g_scores[(size_t)BATCH * SEQ * SEQ];           // 256 MB

// ---------------------------------------------------------------------------
// split helpers
// ---------------------------------------------------------------------------
// bf16: f = hi + lo, packed pairs into bf16x2 words (low = f0)
__device__ __forceinline__ void splitb(float f0, float f1, uint32_t& hi, uint32_t& lo) {
    asm("cvt.rn.bf16x2.f32 %0, %2, %1;" : "=r"(hi) : "f"(f0), "f"(f1));
    float h0 = __uint_as_float(hi << 16);
    float h1 = __uint_as_float(hi & 0xffff0000u);
    float l0 = f0 - h0;
    float l1 = f1 - h1;
    asm("cvt.rn.bf16x2.f32 %0, %2, %1;" : "=r"(lo) : "f"(l0), "f"(l1));
}

// fp16: f = hi + lo, packed pairs into f16x2 words (low = f0)
__device__ __forceinline__ void splith(float f0, float f1, uint32_t& hi, uint32_t& lo) {
    __half2 h = __floats2half2_rn(f0, f1);
    hi = *reinterpret_cast<uint32_t*>(&h);
    float g0 = __low2float(h), g1 = __high2float(h);
    __half2 l = __floats2half2_rn(f0 - g0, f1 - g1);
    lo = *reinterpret_cast<uint32_t*>(&l);
}

__device__ __forceinline__ uint32_t packh(float f0, float f1) {
    __half2 h = __floats2half2_rn(f0, f1);
    return *reinterpret_cast<uint32_t*>(&h);
}

__device__ __forceinline__ void mma_bf(float c[4],
                                       uint32_t a0, uint32_t a1, uint32_t a2, uint32_t a3,
                                       uint32_t b0, uint32_t b1) {
    asm volatile(
        "mma.sync.aligned.m16n8k16.row.col.f32.bf16.bf16.f32 "
        "{%0,%1,%2,%3}, {%4,%5,%6,%7}, {%8,%9}, {%0,%1,%2,%3};\n"
        : "+f"(c[0]), "+f"(c[1]), "+f"(c[2]), "+f"(c[3])
        : "r"(a0), "r"(a1), "r"(a2), "r"(a3), "r"(b0), "r"(b1));
}

__device__ __forceinline__ void mma_hf(float c[4],
                                       uint32_t a0, uint32_t a1, uint32_t a2, uint32_t a3,
                                       uint32_t b0, uint32_t b1) {
    asm volatile(
        "mma.sync.aligned.m16n8k16.row.col.f32.f16.f16.f32 "
        "{%0,%1,%2,%3}, {%4,%5,%6,%7}, {%8,%9}, {%0,%1,%2,%3};\n"
        : "+f"(c[0]), "+f"(c[1]), "+f"(c[2]), "+f"(c[3])
        : "r"(a0), "r"(a1), "r"(a2), "r"(a3), "r"(b0), "r"(b1));
}

// ---------------------------------------------------------------------------
// GEMM NT, double-buffered, BM=BN=128, BK=16 floats, 128 threads (2x2 warps,
// warp tile 64x64), [row][12] smem layout (conflict-free).
//   F16=0: bf16 3-term (A hi/lo x B hi/lo, drop lo*lo): ~fp32 accuracy.
//   F16=1: fp16 2-term (A hi/lo exact x B single fp16): ~5e-4 accuracy.
// tout=1: write C transposed per batch (used for the V projection -> Vt).
// Dynamic smem: F16=0: 48KB, F16=1: 36KB.
// ---------------------------------------------------------------------------
#define STG 1536   // uint32 per buffer per array: 128*12

template<int F16>
__global__ void __launch_bounds__(128) gemm_nt(
    const float* __restrict__ A, const float* __restrict__ B, float* __restrict__ C,
    int lda, int ldb, int ldc, int Kdim,
    long long sA_, long long sB_, long long sC_, int tout)
{
    extern __shared__ __align__(16) uint32_t dsm[];
    uint32_t* sAhi = dsm;                 // [2][STG]
    uint32_t* sAlo = dsm + 2 * STG;       // [2][STG]
    uint32_t* sBhi = dsm + 4 * STG;       // [2][STG]  (F16=1: the only B array)
    uint32_t* sBlo = dsm + 6 * STG;       // [2][STG]  (F16=0 only)

    const float* Ag = A + (long long)blockIdx.z * sA_ + (long long)blockIdx.y * 128 * lda;
    const float* Bg = B + (long long)blockIdx.z * sB_ + (long long)blockIdx.x * 128 * ldb;

    const int tid  = threadIdx.x;
    const int warp = tid >> 5, lane = tid & 31;
    const int wm = (warp >> 1) * 64, wn = (warp & 1) * 64;
    const int lr = lane >> 2, lc = lane & 3;

    // staging coords: thread covers rows p*32 + (tid>>2), float cols (tid&3)*4
    const int rs = tid >> 2;
    const int cs = (tid & 3) * 4;        // float col
    const int cw = (tid & 3) * 2;        // packed word col

    float acc[4][8][4] = {};

    float4 va[4], vb[4];
    auto load_gmem = [&](int k0) {
#pragma unroll
        for (int p = 0; p < 4; p++) {
            va[p] = *(const float4*)(Ag + (long long)(rs + p * 32) * lda + k0 + cs);
            vb[p] = *(const float4*)(Bg + (long long)(rs + p * 32) * ldb + k0 + cs);
        }
    };
    auto store_smem = [&](int buf) {
        uint32_t* pAh = sAhi + buf * STG;
        uint32_t* pAl = sAlo + buf * STG;
        uint32_t* pBh = sBhi + buf * STG;
        uint32_t* pBl = sBlo + buf * STG;
#pragma unroll
        for (int p = 0; p < 4; p++) {
            int ro = (rs + p * 32) * 12;
            uint32_t h0, l0, h1, l1;
            if (F16) {
                splith(va[p].x, va[p].y, h0, l0);
                splith(va[p].z, va[p].w, h1, l1);
                pAh[ro + cw] = h0;  pAh[ro + cw + 1] = h1;
                pAl[ro + cw] = l0;  pAl[ro + cw + 1] = l1;
                pBh[ro + cw]     = packh(vb[p].x, vb[p].y);
                pBh[ro + cw + 1] = packh(vb[p].z, vb[p].w);
            } else {
                splitb(va[p].x, va[p].y, h0, l0);
                splitb(va[p].z, va[p].w, h1, l1);
                pAh[ro + cw] = h0;  pAh[ro + cw + 1] = h1;
                pAl[ro + cw] = l0;  pAl[ro + cw + 1] = l1;
                splitb(vb[p].x, vb[p].y, h0, l0);
                splitb(vb[p].z, vb[p].w, h1, l1);
                pBh[ro + cw] = h0;  pBh[ro + cw + 1] = h1;
                pBl[ro + cw] = l0;  pBl[ro + cw + 1] = l1;
            }
        }
    };
    auto compute = [&](int buf) {
        const uint32_t* pAh = sAhi + buf * STG;
        const uint32_t* pAl = sAlo + buf * STG;
        const uint32_t* pBh = sBhi + buf * STG;
        const uint32_t* pBl = sBlo + buf * STG;
        uint32_t ah[4][4], al[4][4];
#pragma unroll
        for (int mi = 0; mi < 4; mi++) {
            int r0 = (wm + mi * 16 + lr) * 12;
            ah[mi][0] = pAh[r0       + lc    ];  al[mi][0] = pAl[r0       + lc    ];
            ah[mi][1] = pAh[r0 + 96  + lc    ];  al[mi][1] = pAl[r0 + 96  + lc    ];
            ah[mi][2] = pAh[r0       + lc + 4];  al[mi][2] = pAl[r0       + lc + 4];
            ah[mi][3] = pAh[r0 + 96  + lc + 4];  al[mi][3] = pAl[r0 + 96  + lc + 4];
        }
#pragma unroll
        for (int ni = 0; ni < 8; ni++) {
            int n0 = (wn + ni * 8 + lr) * 12;
            uint32_t bh0 = pBh[n0 + lc], bh1 = pBh[n0 + lc + 4];
            if (F16) {
#pragma unroll
                for (int mi = 0; mi < 4; mi++) {
                    mma_hf(acc[mi][ni], ah[mi][0], ah[mi][1], ah[mi][2], ah[mi][3], bh0, bh1);
                    mma_hf(acc[mi][ni], al[mi][0], al[mi][1], al[mi][2], al[mi][3], bh0, bh1);
                }
            } else {
                uint32_t bl0 = pBl[n0 + lc], bl1 = pBl[n0 + lc + 4];
#pragma unroll
                for (int mi = 0; mi < 4; mi++) {
                    mma_bf(acc[mi][ni], ah[mi][0], ah[mi][1], ah[mi][2], ah[mi][3], bh0, bh1);
                    mma_bf(acc[mi][ni], ah[mi][0], ah[mi][1], ah[mi][2], ah[mi][3], bl0, bl1);
                    mma_bf(acc[mi][ni], al[mi][0], al[mi][1], al[mi][2], al[mi][3], bh0, bh1);
                }
            }
        }
    };

    // prologue
    load_gmem(0);
    store_smem(0);
    __syncthreads();

    int buf = 0;
    for (int k0 = 0; k0 < Kdim; k0 += 16) {
        bool more = (k0 + 16) < Kdim;
        if (more) load_gmem(k0 + 16);      // prefetch overlaps compute
        compute(buf);
        if (more) {
            store_smem(buf ^ 1);
            __syncthreads();
            buf ^= 1;
        }
    }

    if (!tout) {
        float* Cg = C + (long long)blockIdx.z * sC_ + (long long)blockIdx.y * 128 * ldc
                      + (long long)blockIdx.x * 128;
#pragma unroll
        for (int mi = 0; mi < 4; mi++)
#pragma unroll
            for (int ni = 0; ni < 8; ni++) {
                int rr = wm + mi * 16 + lr;
                int cc = wn + ni * 8 + lc * 2;
                *(float2*)(Cg + (long long)rr * ldc + cc)       = make_float2(acc[mi][ni][0], acc[mi][ni][1]);
                *(float2*)(Cg + (long long)(rr + 8) * ldc + cc) = make_float2(acc[mi][ni][2], acc[mi][ni][3]);
            }
    } else {
        // transposed write: global row R = (b,s), col h  ->  C[b][h][s]
#pragma unroll
        for (int mi = 0; mi < 4; mi++)
#pragma unroll
            for (int ni = 0; ni < 8; ni++) {
                int R  = blockIdx.y * 128 + wm + mi * 16 + lr;
                int hc = blockIdx.x * 128 + wn + ni * 8 + lc * 2;
                int b  = R >> 12, s = R & (SEQ - 1);
                float* base = C + (long long)b * HID * SEQ;
                base[(long long)hc * SEQ + s]           = acc[mi][ni][0];
                base[(long long)(hc + 1) * SEQ + s]     = acc[mi][ni][1];
                base[(long long)hc * SEQ + s + 8]       = acc[mi][ni][2];
                base[(long long)(hc + 1) * SEQ + s + 8] = acc[mi][ni][3];
            }
    }
}

// ---------------------------------------------------------------------------
// Row softmax over SEQ=4096, with /sqrt(H) scale folded in.
// ---------------------------------------------------------------------------
__global__ void __launch_bounds__(256) softmax_kernel(float* __restrict__ S, float scale) {
    long long row = blockIdx.x;
    float* p = S + row * (long long)SEQ;
    const int tid = threadIdx.x;

    float4 v[4];
    float m = -3.4e38f;
#pragma unroll
    for (int i = 0; i < 4; i++) {
        v[i] = ((const float4*)p)[tid + i * 256];
        m = fmaxf(m, fmaxf(fmaxf(v[i].x, v[i].y), fmaxf(v[i].z, v[i].w)));
    }

    __shared__ float red[8];
#pragma unroll
    for (int o = 16; o; o >>= 1) m = fmaxf(m, __shfl_xor_sync(0xffffffffu, m, o));
    if ((tid & 31) == 0) red[tid >> 5] = m;
    __syncthreads();
    m = red[0];
#pragma unroll
    for (int i = 1; i < 8; i++) m = fmaxf(m, red[i]);

    float sum = 0.f;
#pragma unroll
    for (int i = 0; i < 4; i++) {
        v[i].x = __expf((v[i].x - m) * scale);
        v[i].y = __expf((v[i].y - m) * scale);
        v[i].z = __expf((v[i].z - m) * scale);
        v[i].w = __expf((v[i].w - m) * scale);
        sum += (v[i].x + v[i].y) + (v[i].z + v[i].w);
    }
#pragma unroll
    for (int o = 16; o; o >>= 1) sum += __shfl_xor_sync(0xffffffffu, sum, o);
    __syncthreads();
    if ((tid & 31) == 0) red[tid >> 5] = sum;
    __syncthreads();
    float tot = 0.f;
#pragma unroll
    for (int i = 0; i < 8; i++) tot += red[i];
    float inv = 1.0f / tot;

#pragma unroll
    for (int i = 0; i < 4; i++) {
        v[i].x *= inv; v[i].y *= inv; v[i].z *= inv; v[i].w *= inv;
        ((float4*)p)[tid + i * 256] = v[i];
    }
}

// ---------------------------------------------------------------------------
// Launcher
// ---------------------------------------------------------------------------
#define SMEM0 49152
#define SMEM1 36864

extern "C" void kernel_launch(void* const* d_in, const int* in_sizes, int n_in,
                              void* d_out, int out_size) {
    const float* x  = (const float*)d_in[0];
    const float* Wq = (const float*)d_in[1];
    const float* Wk = (const float*)d_in[2];
    const float* Wv = (const float*)d_in[3];
    float* out = (float*)d_out;

    float *qp, *sp;
    cudaGetSymbolAddress((void**)&qp, g_qkv);
    cudaGetSymbolAddress((void**)&sp, g_scores);
    float* kp  = qp + (long long)BATCH * SEQ * HID;
    float* vtp = kp + (long long)BATCH * SEQ * HID;     // transposed V: [b][h][s]

    cudaFuncSetAttribute(gemm_nt<0>, cudaFuncAttributeMaxDynamicSharedMemorySize, SMEM0);
    cudaFuncSetAttribute(gemm_nt<1>, cudaFuncAttributeMaxDynamicSharedMemorySize, SMEM1);

    dim3 blk(128);

    // 1) QKV projections (bf16 3-term): y = x W^T; V written transposed
    dim3 gq(HID / 128, (BATCH * SEQ) / 128, 1);
    gemm_nt<0><<<gq, blk, SMEM0>>>(x, Wq, qp,  HID, HID, HID, HID, 0, 0, 0, 0);
    gemm_nt<0><<<gq, blk, SMEM0>>>(x, Wk, kp,  HID, HID, HID, HID, 0, 0, 0, 0);
    gemm_nt<0><<<gq, blk, SMEM0>>>(x, Wv, vtp, HID, HID, HID, HID, 0, 0, 0, 1);

    // 2) S = Q K^T  (fp16 2-term; batched: M=N=4096, K=512)
    dim3 gs(SEQ / 128, SEQ / 128, BATCH);
    gemm_nt<1><<<gs, blk, SMEM1>>>(qp, kp, sp, HID, HID, SEQ, HID,
                                   (long long)SEQ * HID, (long long)SEQ * HID,
                                   (long long)SEQ * SEQ, 0);

    // 3) softmax rows with 1/sqrt(H) scale
    softmax_kernel<<<BATCH * SEQ, 256>>>(sp, 0.044194173824159216f);

    // 4) O = P Vt^T  (fp16 2-term; NT: M=4096, N=512, K=4096, batched)
    dim3 gp(HID / 128, SEQ / 128, BATCH);
    gemm_nt<1><<<gp, blk, SMEM1>>>(sp, vtp, out, SEQ, SEQ, HID, SEQ,
                                   (long long)SEQ * SEQ, (long long)HID * SEQ,
                                   (long long)SEQ * HID, 0);
}

// round 10
// speedup vs baseline: 1.7249x; 1.1833x over previous
#include <cuda_runtime.h>
#include <cuda_bf16.h>
#include <cuda_fp16.h>
#include <cstdint>

#define HID  512
#define BATCH 4
#define SEQ  4096

// Scratch (static device globals; allocation-free per harness rules)
// q | k | vt  (vt stored transposed per batch: [HID][SEQ])
__device__ float g_qkv[(size_t)3 * BATCH * SEQ * HID];          // 96 MB
__device__ float g_scores[(size_t)BATCH * SEQ * SEQ];           // 256 MB

// ---------------------------------------------------------------------------
// helpers
// ---------------------------------------------------------------------------
// bf16: f = hi + lo, packed pairs into bf16x2 words (low = f0)
__device__ __forceinline__ void splitb(float f0, float f1, uint32_t& hi, uint32_t& lo) {
    asm("cvt.rn.bf16x2.f32 %0, %2, %1;" : "=r"(hi) : "f"(f0), "f"(f1));
    float h0 = __uint_as_float(hi << 16);
    float h1 = __uint_as_float(hi & 0xffff0000u);
    float l0 = f0 - h0;
    float l1 = f1 - h1;
    asm("cvt.rn.bf16x2.f32 %0, %2, %1;" : "=r"(lo) : "f"(l0), "f"(l1));
}

__device__ __forceinline__ uint32_t packh(float f0, float f1) {
    __half2 h = __floats2half2_rn(f0, f1);
    return *reinterpret_cast<uint32_t*>(&h);
}

__device__ __forceinline__ void mma_bf(float c[4],
                                       uint32_t a0, uint32_t a1, uint32_t a2, uint32_t a3,
                                       uint32_t b0, uint32_t b1) {
    asm volatile(
        "mma.sync.aligned.m16n8k16.row.col.f32.bf16.bf16.f32 "
        "{%0,%1,%2,%3}, {%4,%5,%6,%7}, {%8,%9}, {%0,%1,%2,%3};\n"
        : "+f"(c[0]), "+f"(c[1]), "+f"(c[2]), "+f"(c[3])
        : "r"(a0), "r"(a1), "r"(a2), "r"(a3), "r"(b0), "r"(b1));
}

__device__ __forceinline__ void mma_hf(float c[4],
                                       uint32_t a0, uint32_t a1, uint32_t a2, uint32_t a3,
                                       uint32_t b0, uint32_t b1) {
    asm volatile(
        "mma.sync.aligned.m16n8k16.row.col.f32.f16.f16.f32 "
        "{%0,%1,%2,%3}, {%4,%5,%6,%7}, {%8,%9}, {%0,%1,%2,%3};\n"
        : "+f"(c[0]), "+f"(c[1]), "+f"(c[2]), "+f"(c[3])
        : "r"(a0), "r"(a1), "r"(a2), "r"(a3), "r"(b0), "r"(b1));
}

// ---------------------------------------------------------------------------
// GEMM NT, double-buffered, BM=BN=128, BK=16 floats, 128 threads (2x2 warps,
// warp tile 64x64), [row][12] smem layout (conflict-free).
//   MODE=0: bf16 3-term (A hi/lo x B hi/lo, drop lo*lo): ~fp32 accuracy. 48KB.
//   MODE=1: fp16 1-term (single rn-fp16 both operands, 1 MMA/tile):
//           ~3e-4 accuracy. 24KB.
// tout=1: write C transposed per batch (used for the V projection -> Vt).
// ---------------------------------------------------------------------------
#define STG 1536   // uint32 per buffer per array: 128*12

template<int MODE>
__global__ void __launch_bounds__(128) gemm_nt(
    const float* __restrict__ A, const float* __restrict__ B, float* __restrict__ C,
    int lda, int ldb, int ldc, int Kdim,
    long long sA_, long long sB_, long long sC_, int tout)
{
    extern __shared__ __align__(16) uint32_t dsm[];
    // MODE=0: A hi | A lo | B hi | B lo     MODE=1: A | B
    uint32_t* sAhi = dsm;                               // [2][STG]
    uint32_t* sAlo = dsm + 2 * STG;                     // MODE=0 only
    uint32_t* sBhi = dsm + (MODE ? 2 : 4) * STG;        // [2][STG]
    uint32_t* sBlo = dsm + 6 * STG;                     // MODE=0 only

    const float* Ag = A + (long long)blockIdx.z * sA_ + (long long)blockIdx.y * 128 * lda;
    const float* Bg = B + (long long)blockIdx.z * sB_ + (long long)blockIdx.x * 128 * ldb;

    const int tid  = threadIdx.x;
    const int warp = tid >> 5, lane = tid & 31;
    const int wm = (warp >> 1) * 64, wn = (warp & 1) * 64;
    const int lr = lane >> 2, lc = lane & 3;

    // staging coords: thread covers rows p*32 + (tid>>2), float cols (tid&3)*4
    const int rs = tid >> 2;
    const int cs = (tid & 3) * 4;        // float col
    const int cw = (tid & 3) * 2;        // packed word col

    float acc[4][8][4] = {};

    float4 va[4], vb[4];
    auto load_gmem = [&](int k0) {
#pragma unroll
        for (int p = 0; p < 4; p++) {
            va[p] = *(const float4*)(Ag + (long long)(rs + p * 32) * lda + k0 + cs);
            vb[p] = *(const float4*)(Bg + (long long)(rs + p * 32) * ldb + k0 + cs);
        }
    };
    auto store_smem = [&](int buf) {
        uint32_t* pAh = sAhi + buf * STG;
        uint32_t* pBh = sBhi + buf * STG;
#pragma unroll
        for (int p = 0; p < 4; p++) {
            int ro = (rs + p * 32) * 12;
            if (MODE == 1) {
                pAh[ro + cw]     = packh(va[p].x, va[p].y);
                pAh[ro + cw + 1] = packh(va[p].z, va[p].w);
                pBh[ro + cw]     = packh(vb[p].x, vb[p].y);
                pBh[ro + cw + 1] = packh(vb[p].z, vb[p].w);
            } else {
                uint32_t* pAl = sAlo + buf * STG;
                uint32_t* pBl = sBlo + buf * STG;
                uint32_t h0, l0, h1, l1;
                splitb(va[p].x, va[p].y, h0, l0);
                splitb(va[p].z, va[p].w, h1, l1);
                pAh[ro + cw] = h0;  pAh[ro + cw + 1] = h1;
                pAl[ro + cw] = l0;  pAl[ro + cw + 1] = l1;
                splitb(vb[p].x, vb[p].y, h0, l0);
                splitb(vb[p].z, vb[p].w, h1, l1);
                pBh[ro + cw] = h0;  pBh[ro + cw + 1] = h1;
                pBl[ro + cw] = l0;  pBl[ro + cw + 1] = l1;
            }
        }
    };
    auto compute = [&](int buf) {
        const uint32_t* pAh = sAhi + buf * STG;
        const uint32_t* pBh = sBhi + buf * STG;
        uint32_t ah[4][4];
#pragma unroll
        for (int mi = 0; mi < 4; mi++) {
            int r0 = (wm + mi * 16 + lr) * 12;
            ah[mi][0] = pAh[r0       + lc    ];
            ah[mi][1] = pAh[r0 + 96  + lc    ];
            ah[mi][2] = pAh[r0       + lc + 4];
            ah[mi][3] = pAh[r0 + 96  + lc + 4];
        }
        if (MODE == 1) {
#pragma unroll
            for (int ni = 0; ni < 8; ni++) {
                int n0 = (wn + ni * 8 + lr) * 12;
                uint32_t b0 = pBh[n0 + lc], b1 = pBh[n0 + lc + 4];
#pragma unroll
                for (int mi = 0; mi < 4; mi++)
                    mma_hf(acc[mi][ni], ah[mi][0], ah[mi][1], ah[mi][2], ah[mi][3], b0, b1);
            }
        } else {
            const uint32_t* pAl = sAlo + buf * STG;
            const uint32_t* pBl = sBlo + buf * STG;
            uint32_t al[4][4];
#pragma unroll
            for (int mi = 0; mi < 4; mi++) {
                int r0 = (wm + mi * 16 + lr) * 12;
                al[mi][0] = pAl[r0       + lc    ];
                al[mi][1] = pAl[r0 + 96  + lc    ];
                al[mi][2] = pAl[r0       + lc + 4];
                al[mi][3] = pAl[r0 + 96  + lc + 4];
            }
#pragma unroll
            for (int ni = 0; ni < 8; ni++) {
                int n0 = (wn + ni * 8 + lr) * 12;
                uint32_t bh0 = pBh[n0 + lc], bh1 = pBh[n0 + lc + 4];
                uint32_t bl0 = pBl[n0 + lc], bl1 = pBl[n0 + lc + 4];
#pragma unroll
                for (int mi = 0; mi < 4; mi++) {
                    mma_bf(acc[mi][ni], ah[mi][0], ah[mi][1], ah[mi][2], ah[mi][3], bh0, bh1);
                    mma_bf(acc[mi][ni], ah[mi][0], ah[mi][1], ah[mi][2], ah[mi][3], bl0, bl1);
                    mma_bf(acc[mi][ni], al[mi][0], al[mi][1], al[mi][2], al[mi][3], bh0, bh1);
                }
            }
        }
    };

    // prologue
    load_gmem(0);
    store_smem(0);
    __syncthreads();

    int buf = 0;
    for (int k0 = 0; k0 < Kdim; k0 += 16) {
        bool more = (k0 + 16) < Kdim;
        if (more) load_gmem(k0 + 16);      // prefetch overlaps compute
        compute(buf);
        if (more) {
            store_smem(buf ^ 1);
            __syncthreads();
            buf ^= 1;
        }
    }

    if (!tout) {
        float* Cg = C + (long long)blockIdx.z * sC_ + (long long)blockIdx.y * 128 * ldc
                      + (long long)blockIdx.x * 128;
#pragma unroll
        for (int mi = 0; mi < 4; mi++)
#pragma unroll
            for (int ni = 0; ni < 8; ni++) {
                int rr = wm + mi * 16 + lr;
                int cc = wn + ni * 8 + lc * 2;
                *(float2*)(Cg + (long long)rr * ldc + cc)       = make_float2(acc[mi][ni][0], acc[mi][ni][1]);
                *(float2*)(Cg + (long long)(rr + 8) * ldc + cc) = make_float2(acc[mi][ni][2], acc[mi][ni][3]);
            }
    } else {
        // transposed write: global row R = (b,s), col h  ->  C[b][h][s]
#pragma unroll
        for (int mi = 0; mi < 4; mi++)
#pragma unroll
            for (int ni = 0; ni < 8; ni++) {
                int R  = blockIdx.y * 128 + wm + mi * 16 + lr;
                int hc = blockIdx.x * 128 + wn + ni * 8 + lc * 2;
                int b  = R >> 12, s = R & (SEQ - 1);
                float* base = C + (long long)b * HID * SEQ;
                base[(long long)hc * SEQ + s]           = acc[mi][ni][0];
                base[(long long)(hc + 1) * SEQ + s]     = acc[mi][ni][1];
                base[(long long)hc * SEQ + s + 8]       = acc[mi][ni][2];
                base[(long long)(hc + 1) * SEQ + s + 8] = acc[mi][ni][3];
            }
    }
}

// ---------------------------------------------------------------------------
// Row softmax over SEQ=4096, with /sqrt(H) scale folded in.
// ---------------------------------------------------------------------------
__global__ void __launch_bounds__(256) softmax_kernel(float* __restrict__ S, float scale) {
    long long row = blockIdx.x;
    float* p = S + row * (long long)SEQ;
    const int tid = threadIdx.x;

    float4 v[4];
    float m = -3.4e38f;
#pragma unroll
    for (int i = 0; i < 4; i++) {
        v[i] = ((const float4*)p)[tid + i * 256];
        m = fmaxf(m, fmaxf(fmaxf(v[i].x, v[i].y), fmaxf(v[i].z, v[i].w)));
    }

    __shared__ float red[8];
#pragma unroll
    for (int o = 16; o; o >>= 1) m = fmaxf(m, __shfl_xor_sync(0xffffffffu, m, o));
    if ((tid & 31) == 0) red[tid >> 5] = m;
    __syncthreads();
    m = red[0];
#pragma unroll
    for (int i = 1; i < 8; i++) m = fmaxf(m, red[i]);

    float sum = 0.f;
#pragma unroll
    for (int i = 0; i < 4; i++) {
        v[i].x = __expf((v[i].x - m) * scale);
        v[i].y = __expf((v[i].y - m) * scale);
        v[i].z = __expf((v[i].z - m) * scale);
        v[i].w = __expf((v[i].w - m) * scale);
        sum += (v[i].x + v[i].y) + (v[i].z + v[i].w);
    }
#pragma unroll
    for (int o = 16; o; o >>= 1) sum += __shfl_xor_sync(0xffffffffu, sum, o);
    __syncthreads();
    if ((tid & 31) == 0) red[tid >> 5] = sum;
    __syncthreads();
    float tot = 0.f;
#pragma unroll
    for (int i = 0; i < 8; i++) tot += red[i];
    float inv = 1.0f / tot;

#pragma unroll
    for (int i = 0; i < 4; i++) {
        v[i].x *= inv; v[i].y *= inv; v[i].z *= inv; v[i].w *= inv;
        ((float4*)p)[tid + i * 256] = v[i];
    }
}

// ---------------------------------------------------------------------------
// Launcher
// ---------------------------------------------------------------------------
#define SMEM0 49152
#define SMEM1 24576

extern "C" void kernel_launch(void* const* d_in, const int* in_sizes, int n_in,
                              void* d_out, int out_size) {
    const float* x  = (const float*)d_in[0];
    const float* Wq = (const float*)d_in[1];
    const float* Wk = (const float*)d_in[2];
    const float* Wv = (const float*)d_in[3];
    float* out = (float*)d_out;

    float *qp, *sp;
    cudaGetSymbolAddress((void**)&qp, g_qkv);
    cudaGetSymbolAddress((void**)&sp, g_scores);
    float* kp  = qp + (long long)BATCH * SEQ * HID;
    float* vtp = kp + (long long)BATCH * SEQ * HID;     // transposed V: [b][h][s]

    cudaFuncSetAttribute(gemm_nt<0>, cudaFuncAttributeMaxDynamicSharedMemorySize, SMEM0);
    cudaFuncSetAttribute(gemm_nt<1>, cudaFuncAttributeMaxDynamicSharedMemorySize, SMEM1);

    dim3 blk(128);

    // 1) QKV projections (bf16 3-term): y = x W^T; V written transposed
    dim3 gq(HID / 128, (BATCH * SEQ) / 128, 1);
    gemm_nt<0><<<gq, blk, SMEM0>>>(x, Wq, qp,  HID, HID, HID, HID, 0, 0, 0, 0);
    gemm_nt<0><<<gq, blk, SMEM0>>>(x, Wk, kp,  HID, HID, HID, HID, 0, 0, 0, 0);
    gemm_nt<0><<<gq, blk, SMEM0>>>(x, Wv, vtp, HID, HID, HID, HID, 0, 0, 0, 1);

    // 2) S = Q K^T  (fp16 1-term; batched: M=N=4096, K=512)
    dim3 gs(SEQ / 128, SEQ / 128, BATCH);
    gemm_nt<1><<<gs, blk, SMEM1>>>(qp, kp, sp, HID, HID, SEQ, HID,
                                   (long long)SEQ * HID, (long long)SEQ * HID,
                                   (long long)SEQ * SEQ, 0);

    // 3) softmax rows with 1/sqrt(H) scale
    softmax_kernel<<<BATCH * SEQ, 256>>>(sp, 0.044194173824159216f);

    // 4) O = P Vt^T  (fp16 1-term; NT: M=4096, N=512, K=4096, batched)
    dim3 gp(HID / 128, SEQ / 128, BATCH);
    gemm_nt<1><<<gp, blk, SMEM1>>>(sp, vtp, out, SEQ, SEQ, HID, SEQ,
                                   (long long)SEQ * SEQ, (long long)HID * SEQ,
                                   (long long)SEQ * HID, 0);
}

// round 11
// speedup vs baseline: 2.3384x; 1.3557x over previous
#include <cuda_runtime.h>
#include <cuda_bf16.h>
#include <cuda_fp16.h>
#include <cstdint>

#define HID  512
#define BATCH 4
#define SEQ  4096

// fp16 intermediates (allocation-free: __device__ globals)
__device__ __half g_q [(size_t)BATCH * SEQ * HID];   // [b*s][h]
__device__ __half g_k [(size_t)BATCH * SEQ * HID];   // [b*s][h]
__device__ __half g_vt[(size_t)BATCH * HID * SEQ];   // [b][h][s]
__device__ __half g_s [(size_t)BATCH * SEQ * SEQ];   // [b][q][k]

// ---------------------------------------------------------------------------
// helpers
// ---------------------------------------------------------------------------
__device__ __forceinline__ void splitb(float f0, float f1, uint32_t& hi, uint32_t& lo) {
    asm("cvt.rn.bf16x2.f32 %0, %2, %1;" : "=r"(hi) : "f"(f0), "f"(f1));
    float h0 = __uint_as_float(hi << 16);
    float h1 = __uint_as_float(hi & 0xffff0000u);
    float l0 = f0 - h0;
    float l1 = f1 - h1;
    asm("cvt.rn.bf16x2.f32 %0, %2, %1;" : "=r"(lo) : "f"(l0), "f"(l1));
}

__device__ __forceinline__ uint32_t packh(float f0, float f1) {
    __half2 h = __floats2half2_rn(f0, f1);
    return *reinterpret_cast<uint32_t*>(&h);
}

__device__ __forceinline__ void mma_bf(float c[4],
                                       uint32_t a0, uint32_t a1, uint32_t a2, uint32_t a3,
                                       uint32_t b0, uint32_t b1) {
    asm volatile(
        "mma.sync.aligned.m16n8k16.row.col.f32.bf16.bf16.f32 "
        "{%0,%1,%2,%3}, {%4,%5,%6,%7}, {%8,%9}, {%0,%1,%2,%3};\n"
        : "+f"(c[0]), "+f"(c[1]), "+f"(c[2]), "+f"(c[3])
        : "r"(a0), "r"(a1), "r"(a2), "r"(a3), "r"(b0), "r"(b1));
}

__device__ __forceinline__ void mma_hf(float c[4],
                                       uint32_t a0, uint32_t a1, uint32_t a2, uint32_t a3,
                                       uint32_t b0, uint32_t b1) {
    asm volatile(
        "mma.sync.aligned.m16n8k16.row.col.f32.f16.f16.f32 "
        "{%0,%1,%2,%3}, {%4,%5,%6,%7}, {%8,%9}, {%0,%1,%2,%3};\n"
        : "+f"(c[0]), "+f"(c[1]), "+f"(c[2]), "+f"(c[3])
        : "r"(a0), "r"(a1), "r"(a2), "r"(a3), "r"(b0), "r"(b1));
}

__device__ __forceinline__ uint32_t s2u(const void* p) {
    uint32_t a;
    asm("{ .reg .u64 t; cvta.to.shared.u64 t, %1; cvt.u32.u64 %0, t; }"
        : "=r"(a) : "l"(p));
    return a;
}

__device__ __forceinline__ void cpa16(uint32_t dst, const void* src) {
    asm volatile("cp.async.cg.shared.global [%0], [%1], 16;"
                 :: "r"(dst), "l"(src) : "memory");
}

// ---------------------------------------------------------------------------
// QKV GEMM (fp32 in, bf16 3-term, fp16 out): C[m,n] = sum_k A[m,k]*B[n,k]
// BM=BN=128, BK=16 floats, 128 threads (2x2 warps, 64x64 warp tile),
// [row][12] smem (conflict-free), double buffered. 48KB.
// tout=1: write transposed per batch: C[b][h][s] (for Vt).
// ---------------------------------------------------------------------------
#define STG 1536

__global__ void __launch_bounds__(128) gemm_qkv(
    const float* __restrict__ A, const float* __restrict__ B, __half* __restrict__ C,
    int lda, int ldb, int ldc, int Kdim, int tout)
{
    extern __shared__ __align__(16) uint32_t dsm[];
    uint32_t* sAhi = dsm;
    uint32_t* sAlo = dsm + 2 * STG;
    uint32_t* sBhi = dsm + 4 * STG;
    uint32_t* sBlo = dsm + 6 * STG;

    const float* Ag = A + (long long)blockIdx.y * 128 * lda;
    const float* Bg = B + (long long)blockIdx.x * 128 * ldb;

    const int tid  = threadIdx.x;
    const int warp = tid >> 5, lane = tid & 31;
    const int wm = (warp >> 1) * 64, wn = (warp & 1) * 64;
    const int lr = lane >> 2, lc = lane & 3;

    const int rs = tid >> 2;
    const int cs = (tid & 3) * 4;
    const int cw = (tid & 3) * 2;

    float acc[4][8][4] = {};
    float4 va[4], vb[4];

    auto load_gmem = [&](int k0) {
#pragma unroll
        for (int p = 0; p < 4; p++) {
            va[p] = *(const float4*)(Ag + (long long)(rs + p * 32) * lda + k0 + cs);
            vb[p] = *(const float4*)(Bg + (long long)(rs + p * 32) * ldb + k0 + cs);
        }
    };
    auto store_smem = [&](int buf) {
        uint32_t* pAh = sAhi + buf * STG;
        uint32_t* pAl = sAlo + buf * STG;
        uint32_t* pBh = sBhi + buf * STG;
        uint32_t* pBl = sBlo + buf * STG;
#pragma unroll
        for (int p = 0; p < 4; p++) {
            int ro = (rs + p * 32) * 12;
            uint32_t h0, l0, h1, l1;
            splitb(va[p].x, va[p].y, h0, l0);
            splitb(va[p].z, va[p].w, h1, l1);
            pAh[ro + cw] = h0;  pAh[ro + cw + 1] = h1;
            pAl[ro + cw] = l0;  pAl[ro + cw + 1] = l1;
            splitb(vb[p].x, vb[p].y, h0, l0);
            splitb(vb[p].z, vb[p].w, h1, l1);
            pBh[ro + cw] = h0;  pBh[ro + cw + 1] = h1;
            pBl[ro + cw] = l0;  pBl[ro + cw + 1] = l1;
        }
    };
    auto compute = [&](int buf) {
        const uint32_t* pAh = sAhi + buf * STG;
        const uint32_t* pAl = sAlo + buf * STG;
        const uint32_t* pBh = sBhi + buf * STG;
        const uint32_t* pBl = sBlo + buf * STG;
        uint32_t ah[4][4], al[4][4];
#pragma unroll
        for (int mi = 0; mi < 4; mi++) {
            int r0 = (wm + mi * 16 + lr) * 12;
            ah[mi][0] = pAh[r0      + lc    ];  al[mi][0] = pAl[r0      + lc    ];
            ah[mi][1] = pAh[r0 + 96 + lc    ];  al[mi][1] = pAl[r0 + 96 + lc    ];
            ah[mi][2] = pAh[r0      + lc + 4];  al[mi][2] = pAl[r0      + lc + 4];
            ah[mi][3] = pAh[r0 + 96 + lc + 4];  al[mi][3] = pAl[r0 + 96 + lc + 4];
        }
#pragma unroll
        for (int ni = 0; ni < 8; ni++) {
            int n0 = (wn + ni * 8 + lr) * 12;
            uint32_t bh0 = pBh[n0 + lc], bh1 = pBh[n0 + lc + 4];
            uint32_t bl0 = pBl[n0 + lc], bl1 = pBl[n0 + lc + 4];
#pragma unroll
            for (int mi = 0; mi < 4; mi++) {
                mma_bf(acc[mi][ni], ah[mi][0], ah[mi][1], ah[mi][2], ah[mi][3], bh0, bh1);
                mma_bf(acc[mi][ni], ah[mi][0], ah[mi][1], ah[mi][2], ah[mi][3], bl0, bl1);
                mma_bf(acc[mi][ni], al[mi][0], al[mi][1], al[mi][2], al[mi][3], bh0, bh1);
            }
        }
    };

    load_gmem(0);
    store_smem(0);
    __syncthreads();

    int buf = 0;
    for (int k0 = 0; k0 < Kdim; k0 += 16) {
        bool more = (k0 + 16) < Kdim;
        if (more) load_gmem(k0 + 16);
        compute(buf);
        if (more) {
            store_smem(buf ^ 1);
            __syncthreads();
            buf ^= 1;
        }
    }

    if (!tout) {
        __half* Cg = C + (long long)blockIdx.y * 128 * ldc + blockIdx.x * 128;
#pragma unroll
        for (int mi = 0; mi < 4; mi++)
#pragma unroll
            for (int ni = 0; ni < 8; ni++) {
                int rr = wm + mi * 16 + lr;
                int cc = wn + ni * 8 + lc * 2;
                *(uint32_t*)(Cg + (long long)rr * ldc + cc)       = packh(acc[mi][ni][0], acc[mi][ni][1]);
                *(uint32_t*)(Cg + (long long)(rr + 8) * ldc + cc) = packh(acc[mi][ni][2], acc[mi][ni][3]);
            }
    } else {
        // transposed: global row R = (b,s), col h -> C[b][h][s]
#pragma unroll
        for (int mi = 0; mi < 4; mi++)
#pragma unroll
            for (int ni = 0; ni < 8; ni++) {
                int R  = blockIdx.y * 128 + wm + mi * 16 + lr;
                int hc = blockIdx.x * 128 + wn + ni * 8 + lc * 2;
                int b  = R >> 12, s = R & (SEQ - 1);
                __half* base = C + (long long)b * HID * SEQ;
                base[(long long)hc * SEQ + s]           = __float2half(acc[mi][ni][0]);
                base[(long long)(hc + 1) * SEQ + s]     = __float2half(acc[mi][ni][1]);
                base[(long long)hc * SEQ + s + 8]       = __float2half(acc[mi][ni][2]);
                base[(long long)(hc + 1) * SEQ + s + 8] = __float2half(acc[mi][ni][3]);
            }
    }
}

// ---------------------------------------------------------------------------
// fp16 GEMM NT with cp.async 3-stage pipeline: C[m,n] = sum_k A[m,k]*B[n,k]
// Operands fp16 in gmem. BM=BN=128, BK=32 halves (64B/row).
// smem per stage: A,B each 128 rows x 80B ([row][20w]: 16 data + 4 pad,
// conflict-free fragment reads). 3 stages x 20KB = 60KB.
// F32OUT=1: write fp32 to C (final O); else fp16.
// ---------------------------------------------------------------------------
#define HSTRD 20
#define HSTG  2560      // words per operand per stage (128*20)

template<int F32OUT>
__global__ void __launch_bounds__(128) gemm_h(
    const __half* __restrict__ A, const __half* __restrict__ B, void* __restrict__ Cv,
    int lda, int ldb, int ldc, int Kdim,
    long long sA_, long long sB_, long long sC_)
{
    extern __shared__ __align__(16) uint32_t dsm[];
    const uint32_t sbase = s2u(dsm);

    const __half* Ag = A + (long long)blockIdx.z * sA_ + (long long)blockIdx.y * 128 * lda;
    const __half* Bg = B + (long long)blockIdx.z * sB_ + (long long)blockIdx.x * 128 * ldb;

    const int tid  = threadIdx.x;
    const int warp = tid >> 5, lane = tid & 31;
    const int wm = (warp >> 1) * 64, wn = (warp & 1) * 64;
    const int lr = lane >> 2, lc = lane & 3;

    const int rs = tid >> 2;         // staging row base
    const int ps = (tid & 3);        // 16B chunk within 64B row

    const int nst = Kdim >> 5;       // K / 32
    float acc[4][8][4] = {};

    auto issue = [&](int s) {
        if (s < nst) {
            const int k0 = s << 5;
            const uint32_t base = sbase + (uint32_t)(s % 3) * (2 * HSTG * 4);
#pragma unroll
            for (int p = 0; p < 4; p++) {
                int row = rs + p * 32;
                cpa16(base + row * 80 + ps * 16,
                      Ag + (long long)row * lda + k0 + ps * 8);
                cpa16(base + HSTG * 4 + row * 80 + ps * 16,
                      Bg + (long long)row * ldb + k0 + ps * 8);
            }
        }
        asm volatile("cp.async.commit_group;" ::: "memory");
    };
    auto compute = [&](int buf) {
        const uint32_t* pA = dsm + buf * 2 * HSTG;
        const uint32_t* pB = pA + HSTG;
#pragma unroll
        for (int kc = 0; kc < 2; kc++) {
            uint32_t a[4][4];
#pragma unroll
            for (int mi = 0; mi < 4; mi++) {
                int r0 = (wm + mi * 16 + lr) * HSTRD + kc * 8;
                a[mi][0] = pA[r0             + lc    ];
                a[mi][1] = pA[r0 + 8 * HSTRD + lc    ];
                a[mi][2] = pA[r0             + lc + 4];
                a[mi][3] = pA[r0 + 8 * HSTRD + lc + 4];
            }
#pragma unroll
            for (int ni = 0; ni < 8; ni++) {
                int n0 = (wn + ni * 8 + lr) * HSTRD + kc * 8;
                uint32_t b0 = pB[n0 + lc], b1 = pB[n0 + lc + 4];
#pragma unroll
                for (int mi = 0; mi < 4; mi++)
                    mma_hf(acc[mi][ni], a[mi][0], a[mi][1], a[mi][2], a[mi][3], b0, b1);
            }
        }
    };

    issue(0);
    issue(1);
    for (int s = 0; s < nst; s++) {
        asm volatile("cp.async.wait_group 1;" ::: "memory");
        __syncthreads();
        issue(s + 2);
        compute(s % 3);
    }

    if (F32OUT) {
        float* Cg = (float*)Cv + (long long)blockIdx.z * sC_
                  + (long long)blockIdx.y * 128 * ldc + blockIdx.x * 128;
#pragma unroll
        for (int mi = 0; mi < 4; mi++)
#pragma unroll
            for (int ni = 0; ni < 8; ni++) {
                int rr = wm + mi * 16 + lr;
                int cc = wn + ni * 8 + lc * 2;
                *(float2*)(Cg + (long long)rr * ldc + cc)       = make_float2(acc[mi][ni][0], acc[mi][ni][1]);
                *(float2*)(Cg + (long long)(rr + 8) * ldc + cc) = make_float2(acc[mi][ni][2], acc[mi][ni][3]);
            }
    } else {
        __half* Cg = (__half*)Cv + (long long)blockIdx.z * sC_
                   + (long long)blockIdx.y * 128 * ldc + blockIdx.x * 128;
#pragma unroll
        for (int mi = 0; mi < 4; mi++)
#pragma unroll
            for (int ni = 0; ni < 8; ni++) {
                int rr = wm + mi * 16 + lr;
                int cc = wn + ni * 8 + lc * 2;
                *(uint32_t*)(Cg + (long long)rr * ldc + cc)       = packh(acc[mi][ni][0], acc[mi][ni][1]);
                *(uint32_t*)(Cg + (long long)(rr + 8) * ldc + cc) = packh(acc[mi][ni][2], acc[mi][ni][3]);
            }
    }
}

// ---------------------------------------------------------------------------
// fp16 row softmax over SEQ=4096 with /sqrt(H) scale folded in.
// 256 threads/row, 16 halves per thread.
// ---------------------------------------------------------------------------
__global__ void __launch_bounds__(256) softmax_h(__half* __restrict__ S, float scale) {
    long long row = blockIdx.x;
    __half* p = S + row * (long long)SEQ;
    const int tid = threadIdx.x;

    uint4 u[2];
    float f[16];
    float m = -3.4e38f;
#pragma unroll
    for (int i = 0; i < 2; i++) {
        u[i] = ((const uint4*)p)[tid + i * 256];
        const __half2* h = (const __half2*)&u[i];
#pragma unroll
        for (int q = 0; q < 4; q++) {
            float2 g = __half22float2(h[q]);
            f[i * 8 + 2 * q]     = g.x;
            f[i * 8 + 2 * q + 1] = g.y;
            m = fmaxf(m, fmaxf(g.x, g.y));
        }
    }

    __shared__ float red[8];
#pragma unroll
    for (int o = 16; o; o >>= 1) m = fmaxf(m, __shfl_xor_sync(0xffffffffu, m, o));
    if ((tid & 31) == 0) red[tid >> 5] = m;
    __syncthreads();
    m = red[0];
#pragma unroll
    for (int i = 1; i < 8; i++) m = fmaxf(m, red[i]);

    float sum = 0.f;
#pragma unroll
    for (int j = 0; j < 16; j++) {
        f[j] = __expf((f[j] - m) * scale);
        sum += f[j];
    }
#pragma unroll
    for (int o = 16; o; o >>= 1) sum += __shfl_xor_sync(0xffffffffu, sum, o);
    __syncthreads();
    if ((tid & 31) == 0) red[tid >> 5] = sum;
    __syncthreads();
    float tot = 0.f;
#pragma unroll
    for (int i = 0; i < 8; i++) tot += red[i];
    float inv = 1.0f / tot;

#pragma unroll
    for (int i = 0; i < 2; i++) {
        __half2* h = (__half2*)&u[i];
#pragma unroll
        for (int q = 0; q < 4; q++)
            h[q] = __floats2half2_rn(f[i * 8 + 2 * q] * inv, f[i * 8 + 2 * q + 1] * inv);
        ((uint4*)p)[tid + i * 256] = u[i];
    }
}

// ---------------------------------------------------------------------------
// Launcher
// ---------------------------------------------------------------------------
#define SMEM_QKV 49152
#define SMEM_H   61440

extern "C" void kernel_launch(void* const* d_in, const int* in_sizes, int n_in,
                              void* d_out, int out_size) {
    const float* x  = (const float*)d_in[0];
    const float* Wq = (const float*)d_in[1];
    const float* Wk = (const float*)d_in[2];
    const float* Wv = (const float*)d_in[3];
    float* out = (float*)d_out;

    __half *qp, *kp, *vtp, *sp;
    cudaGetSymbolAddress((void**)&qp,  g_q);
    cudaGetSymbolAddress((void**)&kp,  g_k);
    cudaGetSymbolAddress((void**)&vtp, g_vt);
    cudaGetSymbolAddress((void**)&sp,  g_s);

    cudaFuncSetAttribute(gemm_qkv,  cudaFuncAttributeMaxDynamicSharedMemorySize, SMEM_QKV);
    cudaFuncSetAttribute(gemm_h<0>, cudaFuncAttributeMaxDynamicSharedMemorySize, SMEM_H);
    cudaFuncSetAttribute(gemm_h<1>, cudaFuncAttributeMaxDynamicSharedMemorySize, SMEM_H);

    dim3 blk(128);

    // 1) QKV projections (bf16 3-term, fp16 out); V transposed -> g_vt
    dim3 gq(HID / 128, (BATCH * SEQ) / 128, 1);
    gemm_qkv<<<gq, blk, SMEM_QKV>>>(x, Wq, qp,  HID, HID, HID, HID, 0);
    gemm_qkv<<<gq, blk, SMEM_QKV>>>(x, Wk, kp,  HID, HID, HID, HID, 0);
    gemm_qkv<<<gq, blk, SMEM_QKV>>>(x, Wv, vtp, HID, HID, HID, HID, 1);

    // 2) S = Q K^T (fp16 in/out; batched M=N=4096, K=512)
    dim3 gs(SEQ / 128, SEQ / 128, BATCH);
    gemm_h<0><<<gs, blk, SMEM_H>>>(qp, kp, sp, HID, HID, SEQ, HID,
                                   (long long)SEQ * HID, (long long)SEQ * HID,
                                   (long long)SEQ * SEQ);

    // 3) softmax rows (fp16 in/out) with 1/sqrt(H) scale
    softmax_h<<<BATCH * SEQ, 256>>>(sp, 0.044194173824159216f);

    // 4) O = P Vt^T (fp16 in, fp32 out; NT: M=4096, N=512, K=4096)
    dim3 gp(HID / 128, SEQ / 128, BATCH);
    gemm_h<1><<<gp, blk, SMEM_H>>>(sp, vtp, out, SEQ, SEQ, HID, SEQ,
                                   (long long)SEQ * SEQ, (long long)HID * SEQ,
                                   (long long)SEQ * HID);
}

// round 12
// speedup vs baseline: 2.6090x; 1.1157x over previous
#include <cuda_runtime.h>
#include <cuda_fp16.h>
#include <cstdint>

#define HID  512
#define BATCH 4
#define SEQ  4096

// fp16 intermediates (allocation-free: __device__ globals)
__device__ __half g_xh[(size_t)BATCH * SEQ * HID];   // fp16 copy of x
__device__ __half g_wh[(size_t)3 * HID * HID];       // fp16 Wq|Wk|Wv
__device__ __half g_q [(size_t)BATCH * SEQ * HID];   // [b*s][h]
__device__ __half g_k [(size_t)BATCH * SEQ * HID];   // [b*s][h]
__device__ __half g_vt[(size_t)BATCH * HID * SEQ];   // [b][h][s]
__device__ __half g_s [(size_t)BATCH * SEQ * SEQ];   // [b][q][k]

// ---------------------------------------------------------------------------
// helpers
// ---------------------------------------------------------------------------
__device__ __forceinline__ uint32_t packh(float f0, float f1) {
    __half2 h = __floats2half2_rn(f0, f1);
    return *reinterpret_cast<uint32_t*>(&h);
}

__device__ __forceinline__ void mma_hf(float c[4],
                                       uint32_t a0, uint32_t a1, uint32_t a2, uint32_t a3,
                                       uint32_t b0, uint32_t b1) {
    asm volatile(
        "mma.sync.aligned.m16n8k16.row.col.f32.f16.f16.f32 "
        "{%0,%1,%2,%3}, {%4,%5,%6,%7}, {%8,%9}, {%0,%1,%2,%3};\n"
        : "+f"(c[0]), "+f"(c[1]), "+f"(c[2]), "+f"(c[3])
        : "r"(a0), "r"(a1), "r"(a2), "r"(a3), "r"(b0), "r"(b1));
}

__device__ __forceinline__ uint32_t s2u(const void* p) {
    uint32_t a;
    asm("{ .reg .u64 t; cvta.to.shared.u64 t, %1; cvt.u32.u64 %0, t; }"
        : "=r"(a) : "l"(p));
    return a;
}

__device__ __forceinline__ void cpa16(uint32_t dst, const void* src) {
    asm volatile("cp.async.cg.shared.global [%0], [%1], 16;"
                 :: "r"(dst), "l"(src) : "memory");
}

// ---------------------------------------------------------------------------
// fp32 -> fp16 conversion (vectorized, 4 per thread)
// ---------------------------------------------------------------------------
__global__ void __launch_bounds__(256) f2h(const float* __restrict__ s,
                                           __half* __restrict__ d, int n) {
    int i = (blockIdx.x * 256 + threadIdx.x) * 4;
    if (i < n) {
        float4 v = *(const float4*)(s + i);
        uint2 u;
        u.x = packh(v.x, v.y);
        u.y = packh(v.z, v.w);
        *(uint2*)(d + i) = u;
    }
}

// ---------------------------------------------------------------------------
// fp16 GEMM NT, cp.async 3-stage pipeline: C[m,n] = sum_k A[m,k]*B[n,k]
// BM=128, BN in {128,256}, BK=32 halves (64B rows), THREADS=BN,
// warp tile 64x64. smem/stage: (128+BN) rows x 80B ([row][20w]: conflict-free).
// OUTMODE: 0 = fp16 out, 1 = fp32 out (final O), 2 = fp16 transposed (Vt).
// ---------------------------------------------------------------------------
#define HSTRD 20

template<int BN, int OUTMODE>
__global__ void __launch_bounds__(BN) gemm_h(
    const __half* __restrict__ A, const __half* __restrict__ B, void* __restrict__ Cv,
    int lda, int ldb, int ldc, int Kdim,
    long long sA_, long long sB_, long long sC_)
{
    extern __shared__ __align__(16) uint32_t dsm[];
    const uint32_t sbase = s2u(dsm);

    constexpr int THREADS = BN;
    constexpr int NCOL    = BN / 64;          // warp columns
    constexpr int ROWSTEP = THREADS / 4;
    constexpr int AP      = 128 / ROWSTEP;    // A loader passes
    constexpr int BP      = BN / ROWSTEP;     // B loader passes
    constexpr int STAGEB  = (128 + BN) * 80;  // stage bytes
    constexpr int STAGEW  = (128 + BN) * 20;  // stage words
    constexpr int BOFFW   = 128 * 20;         // B word offset within stage

    const __half* Ag = A + (long long)blockIdx.z * sA_ + (long long)blockIdx.y * 128 * lda;
    const __half* Bg = B + (long long)blockIdx.z * sB_ + (long long)blockIdx.x * BN * ldb;

    const int tid  = threadIdx.x;
    const int warp = tid >> 5, lane = tid & 31;
    const int wm = (warp / NCOL) * 64, wn = (warp % NCOL) * 64;
    const int lr = lane >> 2, lc = lane & 3;

    const int rs = tid >> 2;         // loader row base
    const int ps = tid & 3;          // 16B chunk within 64B row

    const int nst = Kdim >> 5;       // K / 32
    float acc[4][8][4] = {};

    auto issue = [&](int s) {
        if (s < nst) {
            const int k0 = s << 5;
            const uint32_t base = sbase + (uint32_t)(s % 3) * STAGEB;
#pragma unroll
            for (int p = 0; p < AP; p++) {
                int row = rs + p * ROWSTEP;
                cpa16(base + row * 80 + ps * 16,
                      Ag + (long long)row * lda + k0 + ps * 8);
            }
#pragma unroll
            for (int p = 0; p < BP; p++) {
                int row = rs + p * ROWSTEP;
                cpa16(base + 128 * 80 + row * 80 + ps * 16,
                      Bg + (long long)row * ldb + k0 + ps * 8);
            }
        }
        asm volatile("cp.async.commit_group;" ::: "memory");
    };
    auto compute = [&](int buf) {
        const uint32_t* pA = dsm + buf * STAGEW;
        const uint32_t* pB = pA + BOFFW;
#pragma unroll
        for (int kc = 0; kc < 2; kc++) {
            uint32_t a[4][4];
#pragma unroll
            for (int mi = 0; mi < 4; mi++) {
                int r0 = (wm + mi * 16 + lr) * HSTRD + kc * 8;
                a[mi][0] = pA[r0             + lc    ];
                a[mi][1] = pA[r0 + 8 * HSTRD + lc    ];
                a[mi][2] = pA[r0             + lc + 4];
                a[mi][3] = pA[r0 + 8 * HSTRD + lc + 4];
            }
#pragma unroll
            for (int ni = 0; ni < 8; ni++) {
                int n0 = (wn + ni * 8 + lr) * HSTRD + kc * 8;
                uint32_t b0 = pB[n0 + lc], b1 = pB[n0 + lc + 4];
#pragma unroll
                for (int mi = 0; mi < 4; mi++)
                    mma_hf(acc[mi][ni], a[mi][0], a[mi][1], a[mi][2], a[mi][3], b0, b1);
            }
        }
    };

    issue(0);
    issue(1);
    for (int s = 0; s < nst; s++) {
        asm volatile("cp.async.wait_group 1;" ::: "memory");
        __syncthreads();
        issue(s + 2);
        compute(s % 3);
    }

    if (OUTMODE == 1) {
        float* Cg = (float*)Cv + (long long)blockIdx.z * sC_
                  + (long long)blockIdx.y * 128 * ldc + (long long)blockIdx.x * BN;
#pragma unroll
        for (int mi = 0; mi < 4; mi++)
#pragma unroll
            for (int ni = 0; ni < 8; ni++) {
                int rr = wm + mi * 16 + lr;
                int cc = wn + ni * 8 + lc * 2;
                *(float2*)(Cg + (long long)rr * ldc + cc)       = make_float2(acc[mi][ni][0], acc[mi][ni][1]);
                *(float2*)(Cg + (long long)(rr + 8) * ldc + cc) = make_float2(acc[mi][ni][2], acc[mi][ni][3]);
            }
    } else if (OUTMODE == 0) {
        __half* Cg = (__half*)Cv + (long long)blockIdx.z * sC_
                   + (long long)blockIdx.y * 128 * ldc + (long long)blockIdx.x * BN;
#pragma unroll
        for (int mi = 0; mi < 4; mi++)
#pragma unroll
            for (int ni = 0; ni < 8; ni++) {
                int rr = wm + mi * 16 + lr;
                int cc = wn + ni * 8 + lc * 2;
                *(uint32_t*)(Cg + (long long)rr * ldc + cc)       = packh(acc[mi][ni][0], acc[mi][ni][1]);
                *(uint32_t*)(Cg + (long long)(rr + 8) * ldc + cc) = packh(acc[mi][ni][2], acc[mi][ni][3]);
            }
    } else {
        // OUTMODE 2: transposed fp16: row R = (b,s), col h -> C[b][h][s]
        __half* C = (__half*)Cv;
#pragma unroll
        for (int mi = 0; mi < 4; mi++)
#pragma unroll
            for (int ni = 0; ni < 8; ni++) {
                int R  = blockIdx.y * 128 + wm + mi * 16 + lr;
                int hc = blockIdx.x * BN + wn + ni * 8 + lc * 2;
                int b  = R >> 12, s = R & (SEQ - 1);
                __half* base = C + (long long)b * HID * SEQ;
                base[(long long)hc * SEQ + s]           = __float2half(acc[mi][ni][0]);
                base[(long long)(hc + 1) * SEQ + s]     = __float2half(acc[mi][ni][1]);
                base[(long long)hc * SEQ + s + 8]       = __float2half(acc[mi][ni][2]);
                base[(long long)(hc + 1) * SEQ + s + 8] = __float2half(acc[mi][ni][3]);
            }
    }
}

// ---------------------------------------------------------------------------
// fp16 row softmax over SEQ=4096 with /sqrt(H) scale folded in.
// ---------------------------------------------------------------------------
__global__ void __launch_bounds__(256) softmax_h(__half* __restrict__ S, float scale) {
    long long row = blockIdx.x;
    __half* p = S + row * (long long)SEQ;
    const int tid = threadIdx.x;

    uint4 u[2];
    float f[16];
    float m = -3.4e38f;
#pragma unroll
    for (int i = 0; i < 2; i++) {
        u[i] = ((const uint4*)p)[tid + i * 256];
        const __half2* h = (const __half2*)&u[i];
#pragma unroll
        for (int q = 0; q < 4; q++) {
            float2 g = __half22float2(h[q]);
            f[i * 8 + 2 * q]     = g.x;
            f[i * 8 + 2 * q + 1] = g.y;
            m = fmaxf(m, fmaxf(g.x, g.y));
        }
    }

    __shared__ float red[8];
#pragma unroll
    for (int o = 16; o; o >>= 1) m = fmaxf(m, __shfl_xor_sync(0xffffffffu, m, o));
    if ((tid & 31) == 0) red[tid >> 5] = m;
    __syncthreads();
    m = red[0];
#pragma unroll
    for (int i = 1; i < 8; i++) m = fmaxf(m, red[i]);

    float sum = 0.f;
#pragma unroll
    for (int j = 0; j < 16; j++) {
        f[j] = __expf((f[j] - m) * scale);
        sum += f[j];
    }
#pragma unroll
    for (int o = 16; o; o >>= 1) sum += __shfl_xor_sync(0xffffffffu, sum, o);
    __syncthreads();
    if ((tid & 31) == 0) red[tid >> 5] = sum;
    __syncthreads();
    float tot = 0.f;
#pragma unroll
    for (int i = 0; i < 8; i++) tot += red[i];
    float inv = 1.0f / tot;

#pragma unroll
    for (int i = 0; i < 2; i++) {
        __half2* h = (__half2*)&u[i];
#pragma unroll
        for (int q = 0; q < 4; q++)
            h[q] = __floats2half2_rn(f[i * 8 + 2 * q] * inv, f[i * 8 + 2 * q + 1] * inv);
        ((uint4*)p)[tid + i * 256] = u[i];
    }
}

// ---------------------------------------------------------------------------
// Launcher
// ---------------------------------------------------------------------------
#define SM128 61440    // 3 * (128+128) * 80
#define SM256 92160    // 3 * (128+256) * 80

extern "C" void kernel_launch(void* const* d_in, const int* in_sizes, int n_in,
                              void* d_out, int out_size) {
    const float* x  = (const float*)d_in[0];
    const float* Wq = (const float*)d_in[1];
    const float* Wk = (const float*)d_in[2];
    const float* Wv = (const float*)d_in[3];
    float* out = (float*)d_out;

    __half *xh, *wh, *qp, *kp, *vtp, *sp;
    cudaGetSymbolAddress((void**)&xh,  g_xh);
    cudaGetSymbolAddress((void**)&wh,  g_wh);
    cudaGetSymbolAddress((void**)&qp,  g_q);
    cudaGetSymbolAddress((void**)&kp,  g_k);
    cudaGetSymbolAddress((void**)&vtp, g_vt);
    cudaGetSymbolAddress((void**)&sp,  g_s);
    __half* whq = wh;
    __half* whk = wh + (size_t)HID * HID;
    __half* whv = wh + (size_t)2 * HID * HID;

    cudaFuncSetAttribute(gemm_h<128,0>, cudaFuncAttributeMaxDynamicSharedMemorySize, SM128);
    cudaFuncSetAttribute(gemm_h<128,1>, cudaFuncAttributeMaxDynamicSharedMemorySize, SM128);
    cudaFuncSetAttribute(gemm_h<128,2>, cudaFuncAttributeMaxDynamicSharedMemorySize, SM128);
    cudaFuncSetAttribute(gemm_h<256,0>, cudaFuncAttributeMaxDynamicSharedMemorySize, SM256);

    // 0) convert inputs to fp16
    int nx = BATCH * SEQ * HID;
    int nw = HID * HID;
    f2h<<<nx / 1024, 256>>>(x,  xh,  nx);
    f2h<<<nw / 1024, 256>>>(Wq, whq, nw);
    f2h<<<nw / 1024, 256>>>(Wk, whk, nw);
    f2h<<<nw / 1024, 256>>>(Wv, whv, nw);

    // 1) QKV projections (fp16 1-term): y = xh Wh^T; V transposed -> g_vt
    dim3 gq(HID / 128, (BATCH * SEQ) / 128, 1);
    gemm_h<128,0><<<gq, 128, SM128>>>(xh, whq, qp,  HID, HID, HID, HID, 0, 0, 0);
    gemm_h<128,0><<<gq, 128, SM128>>>(xh, whk, kp,  HID, HID, HID, HID, 0, 0, 0);
    gemm_h<128,2><<<gq, 128, SM128>>>(xh, whv, vtp, HID, HID, HID, HID, 0, 0, 0);

    // 2) S = Q K^T (fp16; BN=256; batched M=N=4096, K=512)
    dim3 gs(SEQ / 256, SEQ / 128, BATCH);
    gemm_h<256,0><<<gs, 256, SM256>>>(qp, kp, sp, HID, HID, SEQ, HID,
                                      (long long)SEQ * HID, (long long)SEQ * HID,
                                      (long long)SEQ * SEQ);

    // 3) softmax rows (fp16) with 1/sqrt(H) scale
    softmax_h<<<BATCH * SEQ, 256>>>(sp, 0.044194173824159216f);

    // 4) O = P Vt^T (fp16 in, fp32 out; NT: M=4096, N=512, K=4096)
    dim3 gp(HID / 128, SEQ / 128, BATCH);
    gemm_h<128,1><<<gp, 128, SM128>>>(sp, vtp, out, SEQ, SEQ, HID, SEQ,
                                      (long long)SEQ * SEQ, (long long)HID * SEQ,
                                      (long long)SEQ * HID);
}